// round 6
// baseline (speedup 1.0000x reference)
#include <cuda_runtime.h>
#include <cstdint>

// Problem constants
#define NB     2
#define CIN    256
#define NTOK   4096
#define NH     8
#define DH     64
#define CINNER 512         // NH*DH
#define CQKV   1536        // 3*CINNER

// Scratch (allocation-free rule: __device__ globals)
__device__ float g_qkv[NB * CQKV * NTOK];            // [B][1536][N]
__device__ float g_norms[2 * NB * NH * NTOK];        // q2 then k2
__device__ float g_ao[NB * CINNER * NTOK];           // attention output [B][512][N]

// ---------------------------------------------------------------------------
// mma.sync tf32 + cp.async helpers
// ---------------------------------------------------------------------------
__device__ __forceinline__ uint32_t tf32r(float f) {
    uint32_t u;
    asm("cvt.rna.tf32.f32 %0, %1;" : "=r"(u) : "f"(f));
    return u;
}

__device__ __forceinline__ void mma8(float c[4], const uint32_t a[4],
                                     uint32_t b0, uint32_t b1) {
    asm volatile(
        "mma.sync.aligned.m16n8k8.row.col.f32.tf32.tf32.f32 "
        "{%0,%1,%2,%3}, {%4,%5,%6,%7}, {%8,%9}, {%0,%1,%2,%3};"
        : "+f"(c[0]), "+f"(c[1]), "+f"(c[2]), "+f"(c[3])
        : "r"(a[0]), "r"(a[1]), "r"(a[2]), "r"(a[3]), "r"(b0), "r"(b1));
}

__device__ __forceinline__ uint32_t smem_u32(const void* p) {
    uint32_t a;
    asm("{ .reg .u64 t; cvta.to.shared.u64 t, %1; cvt.u32.u64 %0, t; }"
        : "=r"(a) : "l"(p));
    return a;
}

__device__ __forceinline__ void cp16(uint32_t dst, const void* src) {
    asm volatile("cp.async.cg.shared.global [%0], [%1], 16;"
                 :: "r"(dst), "l"(src) : "memory");
}
#define CP_COMMIT() asm volatile("cp.async.commit_group;" ::: "memory")
#define CP_WAIT(n)  asm volatile("cp.async.wait_group %0;" :: "n"(n) : "memory")

// ---------------------------------------------------------------------------
// 3xtf32 tensor-core GEMM, software-pipelined (reg prefetch of next k-tile).
// Y[b][o][n] = sum_c W[o][c] * X[b][c][n], computed as Y^T: A=X^T, B=W.
// CTA: 256 thr = 8 warps; tile 64(n) x 128(o); warp = 32(n) x 32(o); kTile=32.
// ---------------------------------------------------------------------------
__global__ void __launch_bounds__(256, 2) gemm_tc_kernel(
    const float* __restrict__ W,  // [M][K]
    const float* __restrict__ X,  // [B][K][NTOK]
    float* __restrict__ Y,        // [B][M][NTOK]
    int K, long xStride, long yStride)
{
    extern __shared__ float sm[];
    float* XS = sm;               // [c(32)][132] : (hi,lo) pairs at 2n
    float* WS = sm + 32 * 132;    // [o(128)][68] : (hi,lo) pairs at 2c

    const int tid = threadIdx.x;
    const int lane = tid & 31, w = tid >> 5;
    const int quad = lane & 3, g = lane >> 2;
    const int wn = w >> 2, wo = w & 3;
    const int nblk = blockIdx.x * 64;
    const int oblk = blockIdx.y * 128;
    const float* Xb = X + (long)blockIdx.z * xStride;
    float*       Yb = Y + (long)blockIdx.z * yStride;

    const int xcr = tid >> 3, xn0 = (tid & 7) * 8;
    const int wor = tid >> 1, wc0 = (tid & 1) * 16;
    const float* xsrc = Xb + (long)xcr * NTOK + nblk + xn0;
    const float* wsrc = W + (long)(oblk + wor) * K + wc0;

    float acc[2][4][4];
    #pragma unroll
    for (int mt = 0; mt < 2; mt++)
        #pragma unroll
        for (int ot = 0; ot < 4; ot++)
            #pragma unroll
            for (int r = 0; r < 4; r++) acc[mt][ot][r] = 0.f;

    float4 xr0 = *(const float4*)(xsrc);
    float4 xr1 = *(const float4*)(xsrc + 4);
    float4 wr0 = *(const float4*)(wsrc);
    float4 wr1 = *(const float4*)(wsrc + 4);
    float4 wr2 = *(const float4*)(wsrc + 8);
    float4 wr3 = *(const float4*)(wsrc + 12);

    for (int kc = 0; kc < K; kc += 32) {
        __syncthreads();
        {
            float vv[8] = {xr0.x, xr0.y, xr0.z, xr0.w, xr1.x, xr1.y, xr1.z, xr1.w};
            float* dst = XS + xcr * 132 + 2 * xn0;
            #pragma unroll
            for (int e = 0; e < 8; e++) {
                float hi = __uint_as_float(tf32r(vv[e]));
                *(float2*)(dst + 2 * e) = make_float2(hi, vv[e] - hi);
            }
        }
        {
            float vv[16] = {wr0.x, wr0.y, wr0.z, wr0.w, wr1.x, wr1.y, wr1.z, wr1.w,
                            wr2.x, wr2.y, wr2.z, wr2.w, wr3.x, wr3.y, wr3.z, wr3.w};
            float* dst = WS + wor * 68 + 2 * wc0;
            #pragma unroll
            for (int e = 0; e < 16; e++) {
                float hi = __uint_as_float(tf32r(vv[e]));
                *(float2*)(dst + 2 * e) = make_float2(hi, vv[e] - hi);
            }
        }
        __syncthreads();

        if (kc + 32 < K) {
            const float* xs = xsrc + (long)(kc + 32) * NTOK;
            const float* ws = wsrc + kc + 32;
            xr0 = *(const float4*)(xs);
            xr1 = *(const float4*)(xs + 4);
            wr0 = *(const float4*)(ws);
            wr1 = *(const float4*)(ws + 4);
            wr2 = *(const float4*)(ws + 8);
            wr3 = *(const float4*)(ws + 12);
        }

        #pragma unroll
        for (int ks = 0; ks < 4; ks++) {
            uint32_t ah[2][4], al[2][4];
            #pragma unroll
            for (int mt = 0; mt < 2; mt++) {
                int n = 32 * wn + 16 * mt + g;
                const float* base = XS + (8 * ks + quad) * 132 + 2 * n;
                float2 p0 = *(const float2*)(base);
                float2 p1 = *(const float2*)(base + 16);
                float2 p2 = *(const float2*)(base + 4 * 132);
                float2 p3 = *(const float2*)(base + 4 * 132 + 16);
                ah[mt][0] = __float_as_uint(p0.x); al[mt][0] = __float_as_uint(p0.y);
                ah[mt][1] = __float_as_uint(p1.x); al[mt][1] = __float_as_uint(p1.y);
                ah[mt][2] = __float_as_uint(p2.x); al[mt][2] = __float_as_uint(p2.y);
                ah[mt][3] = __float_as_uint(p3.x); al[mt][3] = __float_as_uint(p3.y);
            }
            #pragma unroll
            for (int ot = 0; ot < 4; ot++) {
                int o = 32 * wo + 8 * ot + g;
                const float* base = WS + o * 68 + 2 * (8 * ks + quad);
                float2 b0 = *(const float2*)(base);
                float2 b1 = *(const float2*)(base + 8);
                uint32_t b0h = __float_as_uint(b0.x), b0l = __float_as_uint(b0.y);
                uint32_t b1h = __float_as_uint(b1.x), b1l = __float_as_uint(b1.y);
                #pragma unroll
                for (int mt = 0; mt < 2; mt++) {
                    mma8(acc[mt][ot], al[mt], b0h, b1h);
                    mma8(acc[mt][ot], ah[mt], b0l, b1l);
                    mma8(acc[mt][ot], ah[mt], b0h, b1h);
                }
            }
        }
    }

    #pragma unroll
    for (int mt = 0; mt < 2; mt++)
        #pragma unroll
        for (int ot = 0; ot < 4; ot++) {
            int n = nblk + 32 * wn + 16 * mt + g;
            int o = oblk + 32 * wo + 8 * ot + 2 * quad;
            Yb[(long)o * NTOK + n]           = acc[mt][ot][0];
            Yb[(long)(o + 1) * NTOK + n]     = acc[mt][ot][1];
            Yb[(long)o * NTOK + n + 8]       = acc[mt][ot][2];
            Yb[(long)(o + 1) * NTOK + n + 8] = acc[mt][ot][3];
        }
}

// ---------------------------------------------------------------------------
// Norms: q2[b][h][n], k2[b][h][n]
// ---------------------------------------------------------------------------
__global__ void __launch_bounds__(256) norms_kernel()
{
    int idx = blockIdx.x * 256 + threadIdx.x;
    int n = idx & (NTOK - 1);
    int t = idx >> 12;
    int h = t & 7;
    int pb = t >> 3;
    int part = pb & 1;
    int b = pb >> 1;
    const float* p = g_qkv + ((long)(b * CQKV + part * CINNER + h * DH)) * NTOK + n;
    float s = 0.f;
    #pragma unroll
    for (int d = 0; d < DH; d++) { float v = p[(long)d * NTOK]; s = fmaf(v, v, s); }
    g_norms[(long)part * (NB * NH * NTOK) + (long)(b * NH + h) * NTOK + n] = s;
}

// ---------------------------------------------------------------------------
// Flash distance attention via mma.sync tf32.
// CTA = 256 threads = 8 warps; each warp owns 16 query rows (128 q / CTA).
// cp.async double-buffered raw K/V staging + nt-software-pipelined compute.
// Dynamic smem (floats):
//   KR[2][4096] @0, VR[2][4096] @8192, KF[4128] @16384, VF[4352] @20512,
//   k2s[64] @24864  -> 24928 floats = 99712 B
// ---------------------------------------------------------------------------
__global__ void __launch_bounds__(256, 2) attn_mma_kernel()
{
    extern __shared__ float asm_[];
    float*    KR  = asm_;               // 2 x 64x64 raw K (d-major)
    float*    VR  = asm_ + 8192;        // 2 x 64x64 raw V (dd-major)
    uint32_t* KF  = (uint32_t*)(asm_ + 16384);   // 8*516 fragment order
    uint32_t* VF  = (uint32_t*)(asm_ + 20512);   // 8*544 fragment order
    float*    k2s = asm_ + 24864;

    const uint32_t sb = smem_u32(asm_);
    const int tid  = threadIdx.x;
    const int wid  = tid >> 5;
    const int lane = tid & 31;
    const int quad = lane & 3;
    const int g    = lane >> 2;
    const int n0   = blockIdx.x * 128;
    const int h = blockIdx.y, b = blockIdx.z;
    const int bh = b * NH + h;

    const float* qb  = g_qkv + (long)(b * CQKV + h * DH) * NTOK;
    const float* kb  = g_qkv + (long)(b * CQKV + CINNER + h * DH) * NTOK;
    const float* vb  = g_qkv + (long)(b * CQKV + 2 * CINNER + h * DH) * NTOK;
    const float* k2g = g_norms + (long)NB * NH * NTOK + (long)bh * NTOK;

    const int i0 = n0 + wid * 16 + g;

    // per-thread staging coordinates (shared by cp.async and fragment phases)
    const int sd = tid >> 4, sj4 = (tid & 15) << 2;   // row d, 4 j's; +16 d per it

    uint32_t aq[8][4];
    #pragma unroll
    for (int ks = 0; ks < 8; ks++) {
        int d = quad + 8 * ks;
        aq[ks][0] = tf32r(qb[(long)d * NTOK + i0]);
        aq[ks][1] = tf32r(qb[(long)d * NTOK + i0 + 8]);
        aq[ks][2] = tf32r(qb[(long)(d + 4) * NTOK + i0]);
        aq[ks][3] = tf32r(qb[(long)(d + 4) * NTOK + i0 + 8]);
    }
    const float q2a = g_norms[(long)bh * NTOK + i0];
    const float q2b = g_norms[(long)bh * NTOK + i0 + 8];

    constexpr float LOG2E  = 1.4426950408889634f;
    constexpr float NSHIFT = -12.0f * LOG2E;

    float o[8][4];
    #pragma unroll
    for (int nt = 0; nt < 8; nt++)
        #pragma unroll
        for (int r = 0; r < 4; r++) o[nt][r] = 0.f;
    float lsum0 = 0.f, lsum1 = 0.f;

    const int srcA = (lane & ~3) | (quad >> 1);
    const int srcB = srcA + 2;

    // ---- prologue: cp.async tile 0 into buffer 0 ----
    #pragma unroll
    for (int it = 0; it < 4; it++) {
        int d = sd + it * 16;
        cp16(sb + (uint32_t)(d * 64 + sj4) * 4,               kb + (long)d * NTOK + sj4);
        cp16(sb + (uint32_t)(8192 + d * 64 + sj4) * 4,        vb + (long)d * NTOK + sj4);
    }
    CP_COMMIT();

    for (int kt = 0; kt < NTOK / 64; kt++) {
        const int buf = kt & 1;
        const uint32_t rOff = (uint32_t)buf * 4096u;

        // issue next tile's cp.async, then wait for current tile
        if (kt < NTOK / 64 - 1) {
            const int nk1 = (kt + 1) * 64;
            const uint32_t r1 = (uint32_t)(buf ^ 1) * 4096u;
            #pragma unroll
            for (int it = 0; it < 4; it++) {
                int d = sd + it * 16;
                cp16(sb + (r1 + d * 64 + sj4) * 4,            kb + (long)d * NTOK + nk1 + sj4);
                cp16(sb + (8192 + r1 + d * 64 + sj4) * 4,     vb + (long)d * NTOK + nk1 + sj4);
            }
            CP_COMMIT();
            CP_WAIT(1);
        } else {
            CP_WAIT(0);
        }
        __syncthreads();   // raw tile visible to all; prev compute done with KF/VF

        // ---- fragment staging from raw smem ----
        #pragma unroll
        for (int it = 0; it < 4; it++) {
            int d = sd + it * 16;
            float4 kv = *(const float4*)(KR + rOff + d * 64 + sj4);
            int base = (d >> 3) * 64 + (d & 3) * 2 + ((d >> 2) & 1);
            float v4[4] = {kv.x, kv.y, kv.z, kv.w};
            #pragma unroll
            for (int r = 0; r < 4; r++) {
                int j = sj4 + r;
                KF[(j >> 3) * 516 + base + (j & 7) * 8] = tf32r(v4[r]);
            }
        }
        #pragma unroll
        for (int it = 0; it < 4; it++) {
            int dd = sd + it * 16;
            float4 vv = *(const float4*)(VR + rOff + dd * 64 + sj4);
            int base = (dd >> 3) * 544 + (dd & 7) * 8;
            float v4[4] = {vv.x, vv.y, vv.z, vv.w};
            #pragma unroll
            for (int r = 0; r < 4; r++) {
                int j = sj4 + r;
                VF[base + (j >> 3) * 68 + (j & 3) * 2 + ((j >> 2) & 1)] = tf32r(v4[r]);
            }
        }
        if (tid < 64) k2s[tid] = k2g[kt * 64 + tid];
        __syncthreads();

        // ---- compute: nt-software-pipelined ----
        float ccur[4] = {0.f, 0.f, 0.f, 0.f};
        {
            const uint32_t* kfp = KF + lane * 2;
            #pragma unroll
            for (int ks = 0; ks < 8; ks++) {
                uint2 bb = *(const uint2*)(kfp + ks * 64);
                mma8(ccur, aq[ks], bb.x, bb.y);
            }
        }
        #pragma unroll
        for (int nt = 0; nt < 8; nt++) {
            float cnext[4] = {0.f, 0.f, 0.f, 0.f};
            if (nt < 7) {
                const uint32_t* kfp = KF + (nt + 1) * 516 + lane * 2;
                #pragma unroll
                for (int ks = 0; ks < 8; ks++) {
                    uint2 bb = *(const uint2*)(kfp + ks * 64);
                    mma8(cnext, aq[ks], bb.x, bb.y);
                }
            }

            float k2c0 = k2s[8 * nt + 2 * quad];
            float k2c1 = k2s[8 * nt + 2 * quad + 1];
            float p[4];
            {
                float d2, s;
                d2 = fmaxf(q2a + k2c0 - 2.f * ccur[0], 0.f);
                asm("sqrt.approx.f32 %0, %1;" : "=f"(s) : "f"(d2));
                asm("ex2.approx.f32 %0, %1;" : "=f"(p[0]) : "f"(fmaf(s, LOG2E, NSHIFT)));
                d2 = fmaxf(q2a + k2c1 - 2.f * ccur[1], 0.f);
                asm("sqrt.approx.f32 %0, %1;" : "=f"(s) : "f"(d2));
                asm("ex2.approx.f32 %0, %1;" : "=f"(p[1]) : "f"(fmaf(s, LOG2E, NSHIFT)));
                d2 = fmaxf(q2b + k2c0 - 2.f * ccur[2], 0.f);
                asm("sqrt.approx.f32 %0, %1;" : "=f"(s) : "f"(d2));
                asm("ex2.approx.f32 %0, %1;" : "=f"(p[2]) : "f"(fmaf(s, LOG2E, NSHIFT)));
                d2 = fmaxf(q2b + k2c1 - 2.f * ccur[3], 0.f);
                asm("sqrt.approx.f32 %0, %1;" : "=f"(s) : "f"(d2));
                asm("ex2.approx.f32 %0, %1;" : "=f"(p[3]) : "f"(fmaf(s, LOG2E, NSHIFT)));
            }
            lsum0 += p[0] + p[1];
            lsum1 += p[2] + p[3];

            uint32_t up0 = tf32r(p[0]), up1 = tf32r(p[1]);
            uint32_t up2 = tf32r(p[2]), up3 = tf32r(p[3]);
            uint32_t x0 = __shfl_sync(0xffffffffu, up0, srcA);
            uint32_t x1 = __shfl_sync(0xffffffffu, up1, srcA);
            uint32_t x2 = __shfl_sync(0xffffffffu, up2, srcA);
            uint32_t x3 = __shfl_sync(0xffffffffu, up3, srcA);
            uint32_t y0 = __shfl_sync(0xffffffffu, up0, srcB);
            uint32_t y1 = __shfl_sync(0xffffffffu, up1, srcB);
            uint32_t y2 = __shfl_sync(0xffffffffu, up2, srcB);
            uint32_t y3 = __shfl_sync(0xffffffffu, up3, srcB);
            uint32_t ap[4];
            ap[0] = (quad & 1) ? x1 : x0;
            ap[1] = (quad & 1) ? x3 : x2;
            ap[2] = (quad & 1) ? y1 : y0;
            ap[3] = (quad & 1) ? y3 : y2;

            const uint32_t* vfp = VF + nt * 68 + lane * 2;
            #pragma unroll
            for (int ddnt = 0; ddnt < 8; ddnt++) {
                uint2 vv = *(const uint2*)(vfp + ddnt * 544);
                mma8(o[ddnt], ap, vv.x, vv.y);
            }

            #pragma unroll
            for (int r = 0; r < 4; r++) ccur[r] = cnext[r];
        }
    }

    lsum0 += __shfl_xor_sync(0xffffffffu, lsum0, 1);
    lsum0 += __shfl_xor_sync(0xffffffffu, lsum0, 2);
    lsum1 += __shfl_xor_sync(0xffffffffu, lsum1, 1);
    lsum1 += __shfl_xor_sync(0xffffffffu, lsum1, 2);
    const float inv0 = 1.f / lsum0;
    const float inv1 = 1.f / lsum1;

    float* aob = g_ao + (long)(b * CINNER + h * DH) * NTOK;
    #pragma unroll
    for (int nt = 0; nt < 8; nt++) {
        int dd = 8 * nt + 2 * quad;
        aob[(long)dd * NTOK + i0]           = o[nt][0] * inv0;
        aob[(long)(dd + 1) * NTOK + i0]     = o[nt][1] * inv0;
        aob[(long)dd * NTOK + i0 + 8]       = o[nt][2] * inv1;
        aob[(long)(dd + 1) * NTOK + i0 + 8] = o[nt][3] * inv1;
    }
}

// ---------------------------------------------------------------------------
extern "C" void kernel_launch(void* const* d_in, const int* in_sizes, int n_in,
                              void* d_out, int out_size)
{
    (void)in_sizes; (void)n_in; (void)out_size;
    const float* fmap  = (const float*)d_in[0];   // [2,256,64,64]
    const float* w_qkv = (const float*)d_in[1];   // [1536,256]
    const float* w_out = (const float*)d_in[2];   // [256,512]
    float* out = (float*)d_out;                   // [2,256,64,64]

    void* qkvPtr = nullptr;
    void* aoPtr  = nullptr;
    cudaGetSymbolAddress(&qkvPtr, g_qkv);
    cudaGetSymbolAddress(&aoPtr,  g_ao);

    const int gemmSmem = (32 * 132 + 128 * 68) * (int)sizeof(float);  // 51712
    cudaFuncSetAttribute(gemm_tc_kernel,
                         cudaFuncAttributeMaxDynamicSharedMemorySize, gemmSmem);

    // K1: QKV projection  [1536,256] @ [2,256,4096] -> g_qkv (3xtf32)
    {
        dim3 grid(NTOK / 64, CQKV / 128, NB);
        gemm_tc_kernel<<<grid, 256, gemmSmem>>>(w_qkv, fmap, (float*)qkvPtr,
                                                CIN, (long)CIN * NTOK, (long)CQKV * NTOK);
    }
    // K2: norms
    norms_kernel<<<(NB * NH * 2 * NTOK) / 256, 256>>>();

    // K3: tensor-core (mma.sync tf32) attention, cp.async + nt pipeline
    {
        const int attnSmem = 24928 * (int)sizeof(float);   // 99712
        cudaFuncSetAttribute(attn_mma_kernel,
                             cudaFuncAttributeMaxDynamicSharedMemorySize, attnSmem);
        dim3 grid(NTOK / 128, NH, NB);
        attn_mma_kernel<<<grid, 256, attnSmem>>>();
    }
    // K4: output projection [256,512] @ [2,512,4096] -> out (3xtf32)
    {
        dim3 grid(NTOK / 64, CIN / 128, NB);
        gemm_tc_kernel<<<grid, 256, gemmSmem>>>(w_out, (const float*)aoPtr, out,
                                                CINNER, (long)CINNER * NTOK, (long)CIN * NTOK);
    }
}

// round 7
// speedup vs baseline: 1.3807x; 1.3807x over previous
#include <cuda_runtime.h>
#include <cuda_fp16.h>
#include <cstdint>

// Problem constants
#define NB     2
#define CIN    256
#define NTOK   4096
#define NH     8
#define DH     64
#define CINNER 512         // NH*DH
#define CQKV   1536        // 3*CINNER

// Scratch (allocation-free rule: __device__ globals)
__device__ float g_qkv[NB * CQKV * NTOK];            // [B][1536][N]
__device__ float g_norms[2 * NB * NH * NTOK];        // q2 then k2
__device__ float g_ao[NB * CINNER * NTOK];           // attention output [B][512][N]

// ---------------------------------------------------------------------------
// mma.sync helpers
// ---------------------------------------------------------------------------
__device__ __forceinline__ uint32_t tf32r(float f) {
    uint32_t u;
    asm("cvt.rna.tf32.f32 %0, %1;" : "=r"(u) : "f"(f));
    return u;
}

__device__ __forceinline__ void mma8(float c[4], const uint32_t a[4],
                                     uint32_t b0, uint32_t b1) {
    asm volatile(
        "mma.sync.aligned.m16n8k8.row.col.f32.tf32.tf32.f32 "
        "{%0,%1,%2,%3}, {%4,%5,%6,%7}, {%8,%9}, {%0,%1,%2,%3};"
        : "+f"(c[0]), "+f"(c[1]), "+f"(c[2]), "+f"(c[3])
        : "r"(a[0]), "r"(a[1]), "r"(a[2]), "r"(a[3]), "r"(b0), "r"(b1));
}

__device__ __forceinline__ void mma16(float c[4], const uint32_t a[4],
                                      uint32_t b0, uint32_t b1) {
    asm volatile(
        "mma.sync.aligned.m16n8k16.row.col.f32.f16.f16.f32 "
        "{%0,%1,%2,%3}, {%4,%5,%6,%7}, {%8,%9}, {%0,%1,%2,%3};"
        : "+f"(c[0]), "+f"(c[1]), "+f"(c[2]), "+f"(c[3])
        : "r"(a[0]), "r"(a[1]), "r"(a[2]), "r"(a[3]), "r"(b0), "r"(b1));
}

__device__ __forceinline__ uint32_t packh2(float lo, float hi) {
    __half2 h = __floats2half2_rn(lo, hi);   // .x = lo (low 16 bits)
    return *(uint32_t*)&h;
}

// ---------------------------------------------------------------------------
// 3xtf32 tensor-core GEMM, software-pipelined (reg prefetch of next k-tile).
// ---------------------------------------------------------------------------
__global__ void __launch_bounds__(256, 2) gemm_tc_kernel(
    const float* __restrict__ W,  // [M][K]
    const float* __restrict__ X,  // [B][K][NTOK]
    float* __restrict__ Y,        // [B][M][NTOK]
    int K, long xStride, long yStride)
{
    extern __shared__ float sm[];
    float* XS = sm;               // [c(32)][132]
    float* WS = sm + 32 * 132;    // [o(128)][68]

    const int tid = threadIdx.x;
    const int lane = tid & 31, w = tid >> 5;
    const int quad = lane & 3, g = lane >> 2;
    const int wn = w >> 2, wo = w & 3;
    const int nblk = blockIdx.x * 64;
    const int oblk = blockIdx.y * 128;
    const float* Xb = X + (long)blockIdx.z * xStride;
    float*       Yb = Y + (long)blockIdx.z * yStride;

    const int xcr = tid >> 3, xn0 = (tid & 7) * 8;
    const int wor = tid >> 1, wc0 = (tid & 1) * 16;
    const float* xsrc = Xb + (long)xcr * NTOK + nblk + xn0;
    const float* wsrc = W + (long)(oblk + wor) * K + wc0;

    float acc[2][4][4];
    #pragma unroll
    for (int mt = 0; mt < 2; mt++)
        #pragma unroll
        for (int ot = 0; ot < 4; ot++)
            #pragma unroll
            for (int r = 0; r < 4; r++) acc[mt][ot][r] = 0.f;

    float4 xr0 = *(const float4*)(xsrc);
    float4 xr1 = *(const float4*)(xsrc + 4);
    float4 wr0 = *(const float4*)(wsrc);
    float4 wr1 = *(const float4*)(wsrc + 4);
    float4 wr2 = *(const float4*)(wsrc + 8);
    float4 wr3 = *(const float4*)(wsrc + 12);

    for (int kc = 0; kc < K; kc += 32) {
        __syncthreads();
        {
            float vv[8] = {xr0.x, xr0.y, xr0.z, xr0.w, xr1.x, xr1.y, xr1.z, xr1.w};
            float* dst = XS + xcr * 132 + 2 * xn0;
            #pragma unroll
            for (int e = 0; e < 8; e++) {
                float hi = __uint_as_float(tf32r(vv[e]));
                *(float2*)(dst + 2 * e) = make_float2(hi, vv[e] - hi);
            }
        }
        {
            float vv[16] = {wr0.x, wr0.y, wr0.z, wr0.w, wr1.x, wr1.y, wr1.z, wr1.w,
                            wr2.x, wr2.y, wr2.z, wr2.w, wr3.x, wr3.y, wr3.z, wr3.w};
            float* dst = WS + wor * 68 + 2 * wc0;
            #pragma unroll
            for (int e = 0; e < 16; e++) {
                float hi = __uint_as_float(tf32r(vv[e]));
                *(float2*)(dst + 2 * e) = make_float2(hi, vv[e] - hi);
            }
        }
        __syncthreads();

        if (kc + 32 < K) {
            const float* xs = xsrc + (long)(kc + 32) * NTOK;
            const float* ws = wsrc + kc + 32;
            xr0 = *(const float4*)(xs);
            xr1 = *(const float4*)(xs + 4);
            wr0 = *(const float4*)(ws);
            wr1 = *(const float4*)(ws + 4);
            wr2 = *(const float4*)(ws + 8);
            wr3 = *(const float4*)(ws + 12);
        }

        #pragma unroll
        for (int ks = 0; ks < 4; ks++) {
            uint32_t ah[2][4], al[2][4];
            #pragma unroll
            for (int mt = 0; mt < 2; mt++) {
                int n = 32 * wn + 16 * mt + g;
                const float* base = XS + (8 * ks + quad) * 132 + 2 * n;
                float2 p0 = *(const float2*)(base);
                float2 p1 = *(const float2*)(base + 16);
                float2 p2 = *(const float2*)(base + 4 * 132);
                float2 p3 = *(const float2*)(base + 4 * 132 + 16);
                ah[mt][0] = __float_as_uint(p0.x); al[mt][0] = __float_as_uint(p0.y);
                ah[mt][1] = __float_as_uint(p1.x); al[mt][1] = __float_as_uint(p1.y);
                ah[mt][2] = __float_as_uint(p2.x); al[mt][2] = __float_as_uint(p2.y);
                ah[mt][3] = __float_as_uint(p3.x); al[mt][3] = __float_as_uint(p3.y);
            }
            #pragma unroll
            for (int ot = 0; ot < 4; ot++) {
                int o = 32 * wo + 8 * ot + g;
                const float* base = WS + o * 68 + 2 * (8 * ks + quad);
                float2 b0 = *(const float2*)(base);
                float2 b1 = *(const float2*)(base + 8);
                uint32_t b0h = __float_as_uint(b0.x), b0l = __float_as_uint(b0.y);
                uint32_t b1h = __float_as_uint(b1.x), b1l = __float_as_uint(b1.y);
                #pragma unroll
                for (int mt = 0; mt < 2; mt++) {
                    mma8(acc[mt][ot], al[mt], b0h, b1h);
                    mma8(acc[mt][ot], ah[mt], b0l, b1l);
                    mma8(acc[mt][ot], ah[mt], b0h, b1h);
                }
            }
        }
    }

    #pragma unroll
    for (int mt = 0; mt < 2; mt++)
        #pragma unroll
        for (int ot = 0; ot < 4; ot++) {
            int n = nblk + 32 * wn + 16 * mt + g;
            int o = oblk + 32 * wo + 8 * ot + 2 * quad;
            Yb[(long)o * NTOK + n]           = acc[mt][ot][0];
            Yb[(long)(o + 1) * NTOK + n]     = acc[mt][ot][1];
            Yb[(long)o * NTOK + n + 8]       = acc[mt][ot][2];
            Yb[(long)(o + 1) * NTOK + n + 8] = acc[mt][ot][3];
        }
}

// ---------------------------------------------------------------------------
// Norms: q2[b][h][n], k2[b][h][n]
// ---------------------------------------------------------------------------
__global__ void __launch_bounds__(256) norms_kernel()
{
    int idx = blockIdx.x * 256 + threadIdx.x;
    int n = idx & (NTOK - 1);
    int t = idx >> 12;
    int h = t & 7;
    int pb = t >> 3;
    int part = pb & 1;
    int b = pb >> 1;
    const float* p = g_qkv + ((long)(b * CQKV + part * CINNER + h * DH)) * NTOK + n;
    float s = 0.f;
    #pragma unroll
    for (int d = 0; d < DH; d++) { float v = p[(long)d * NTOK]; s = fmaf(v, v, s); }
    g_norms[(long)part * (NB * NH * NTOK) + (long)(b * NH + h) * NTOK + n] = s;
}

// ---------------------------------------------------------------------------
// Flash distance attention via mma.sync fp16 m16n8k16 (f32 accumulate).
// CTA = 256 threads = 8 warps; each warp owns 16 query rows (128 q / CTA).
// Fixed-shift softmax. No shuffle transpose: QK C-frag packs directly into
// PV A-frag (fp16 layout identity).
// Fragment smem (uint2, strides 133 per nt-block / 33 per k16-block):
//   KW word(nt,ks,q,w=0/1) = fp16x2 {K[16ks+8w+2q][8nt+g], K[..+1][..]}
//   VW word(ddnt,js,q,w)   = fp16x2 {V[16js+8w+2q][8ddnt+g], V[..+1][..]}
// ---------------------------------------------------------------------------
__global__ void __launch_bounds__(256, 2) attn_mma_kernel()
{
    __shared__ uint2 KW[8 * 133];   // 8512 B
    __shared__ uint2 VW[8 * 133];   // 8512 B
    __shared__ float k2s[64];

    const int tid  = threadIdx.x;
    const int wid  = tid >> 5;
    const int lane = tid & 31;
    const int quad = lane & 3;
    const int g    = lane >> 2;
    const int n0   = blockIdx.x * 128;
    const int h = blockIdx.y, b = blockIdx.z;
    const int bh = b * NH + h;

    const float* qb  = g_qkv + (long)(b * CQKV + h * DH) * NTOK;
    const float* kb  = g_qkv + (long)(b * CQKV + CINNER + h * DH) * NTOK;
    const float* vb  = g_qkv + (long)(b * CQKV + 2 * CINNER + h * DH) * NTOK;
    const float* k2g = g_norms + (long)NB * NH * NTOK + (long)bh * NTOK;

    const int i0 = n0 + wid * 16 + g;

    // Q A-fragments (fp16): aq[ks]{a0..a3}, k-block ks covers d = 16ks..16ks+15
    uint32_t aq[4][4];
    #pragma unroll
    for (int ks = 0; ks < 4; ks++) {
        int d0 = 16 * ks + 2 * quad;
        aq[ks][0] = packh2(qb[(long)d0 * NTOK + i0],       qb[(long)(d0 + 1) * NTOK + i0]);
        aq[ks][1] = packh2(qb[(long)d0 * NTOK + i0 + 8],   qb[(long)(d0 + 1) * NTOK + i0 + 8]);
        aq[ks][2] = packh2(qb[(long)(d0 + 8) * NTOK + i0], qb[(long)(d0 + 9) * NTOK + i0]);
        aq[ks][3] = packh2(qb[(long)(d0 + 8) * NTOK + i0 + 8],
                           qb[(long)(d0 + 9) * NTOK + i0 + 8]);
    }
    const float q2a = g_norms[(long)bh * NTOK + i0];
    const float q2b = g_norms[(long)bh * NTOK + i0 + 8];

    constexpr float LOG2E  = 1.4426950408889634f;
    constexpr float NSHIFT = -12.0f * LOG2E;

    float o[8][4];
    #pragma unroll
    for (int nt = 0; nt < 8; nt++)
        #pragma unroll
        for (int r = 0; r < 4; r++) o[nt][r] = 0.f;
    float lsum0 = 0.f, lsum1 = 0.f;

    uint32_t* KWw = (uint32_t*)KW;
    uint32_t* VWw = (uint32_t*)VW;

    for (int kt = 0; kt < NTOK / 64; kt++) {
        const int nk = kt * 64;
        __syncthreads();   // previous iteration done reading KW/VW/k2s

        // ---- stage K (d-pairs): tasks r(0..31) x j4(0..15) ----
        #pragma unroll
        for (int it = 0; it < 2; it++) {
            int task = tid + it * 256;
            int r = task >> 4, j4 = (task & 15) << 2;
            const float* p0 = kb + (long)(2 * r) * NTOK + nk + j4;
            float4 ka = *(const float4*)p0;
            float4 kc = *(const float4*)(p0 + NTOK);
            float va[4] = {ka.x, ka.y, ka.z, ka.w};
            float vc[4] = {kc.x, kc.y, kc.z, kc.w};
            int ks = r >> 3, q_ = r & 3, wsel = (r >> 2) & 1;
            int base = ks * 33 + q_ * 8;
            #pragma unroll
            for (int s = 0; s < 4; s++) {
                int j = j4 + s;
                KWw[((j >> 3) * 133 + base + (j & 7)) * 2 + wsel] = packh2(va[s], vc[s]);
            }
        }
        // ---- stage V (j-pairs): tasks dd(0..63) x j4(0..15) ----
        #pragma unroll
        for (int it = 0; it < 4; it++) {
            int task = tid + it * 256;
            int dd = task >> 4, j4 = (task & 15) << 2;
            float4 v = *(const float4*)(vb + (long)dd * NTOK + nk + j4);
            int ddnt = dd >> 3, g_ = dd & 7;
            int js = j4 >> 4;
            int p0 = (j4 >> 1) & 7;                 // pair index within 16-block
            int base = ddnt * 133 + js * 33 + g_ * 4;
            uint32_t w0 = packh2(v.x, v.y);
            uint32_t w1 = packh2(v.z, v.w);
            VWw[(base + (p0 & 3)) * 2 + (p0 >> 2)]             = w0;
            VWw[(base + ((p0 + 1) & 3)) * 2 + ((p0 + 1) >> 2)] = w1;
        }
        if (tid < 64) k2s[tid] = k2g[nk + tid];
        __syncthreads();

        // ---- compute over nt-pairs ----
        #pragma unroll
        for (int ntp = 0; ntp < 4; ntp++) {
            float c[2][4];
            #pragma unroll
            for (int sub = 0; sub < 2; sub++) {
                int nt = 2 * ntp + sub;
                c[sub][0] = c[sub][1] = c[sub][2] = c[sub][3] = 0.f;
                const uint2* kfp = KW + nt * 133 + quad * 8 + g;
                #pragma unroll
                for (int ks = 0; ks < 4; ks++) {
                    uint2 bb = kfp[ks * 33];
                    mma16(c[sub], aq[ks], bb.x, bb.y);
                }
            }

            // softmax on 16 scores (2 sub-blocks x 4)
            float p[2][4];
            #pragma unroll
            for (int sub = 0; sub < 2; sub++) {
                int nt = 2 * ntp + sub;
                float k2c0 = k2s[8 * nt + 2 * quad];
                float k2c1 = k2s[8 * nt + 2 * quad + 1];
                float d2, s;
                d2 = fmaxf(q2a + k2c0 - 2.f * c[sub][0], 0.f);
                asm("sqrt.approx.f32 %0, %1;" : "=f"(s) : "f"(d2));
                asm("ex2.approx.f32 %0, %1;" : "=f"(p[sub][0]) : "f"(fmaf(s, LOG2E, NSHIFT)));
                d2 = fmaxf(q2a + k2c1 - 2.f * c[sub][1], 0.f);
                asm("sqrt.approx.f32 %0, %1;" : "=f"(s) : "f"(d2));
                asm("ex2.approx.f32 %0, %1;" : "=f"(p[sub][1]) : "f"(fmaf(s, LOG2E, NSHIFT)));
                d2 = fmaxf(q2b + k2c0 - 2.f * c[sub][2], 0.f);
                asm("sqrt.approx.f32 %0, %1;" : "=f"(s) : "f"(d2));
                asm("ex2.approx.f32 %0, %1;" : "=f"(p[sub][2]) : "f"(fmaf(s, LOG2E, NSHIFT)));
                d2 = fmaxf(q2b + k2c1 - 2.f * c[sub][3], 0.f);
                asm("sqrt.approx.f32 %0, %1;" : "=f"(s) : "f"(d2));
                asm("ex2.approx.f32 %0, %1;" : "=f"(p[sub][3]) : "f"(fmaf(s, LOG2E, NSHIFT)));
                lsum0 += p[sub][0] + p[sub][1];
                lsum1 += p[sub][2] + p[sub][3];
            }

            // pack P directly into PV A-fragment (no shuffles needed)
            uint32_t ap[4];
            ap[0] = packh2(p[0][0], p[0][1]);
            ap[1] = packh2(p[0][2], p[0][3]);
            ap[2] = packh2(p[1][0], p[1][1]);
            ap[3] = packh2(p[1][2], p[1][3]);

            // PV over k-block = ntp (16 keys)
            const uint2* vfp = VW + ntp * 33 + lane;
            #pragma unroll
            for (int ddnt = 0; ddnt < 8; ddnt++) {
                uint2 vv = vfp[ddnt * 133];
                mma16(o[ddnt], ap, vv.x, vv.y);
            }
        }
    }

    lsum0 += __shfl_xor_sync(0xffffffffu, lsum0, 1);
    lsum0 += __shfl_xor_sync(0xffffffffu, lsum0, 2);
    lsum1 += __shfl_xor_sync(0xffffffffu, lsum1, 1);
    lsum1 += __shfl_xor_sync(0xffffffffu, lsum1, 2);
    const float inv0 = 1.f / lsum0;
    const float inv1 = 1.f / lsum1;

    float* aob = g_ao + (long)(b * CINNER + h * DH) * NTOK;
    #pragma unroll
    for (int nt = 0; nt < 8; nt++) {
        int dd = 8 * nt + 2 * quad;
        aob[(long)dd * NTOK + i0]           = o[nt][0] * inv0;
        aob[(long)(dd + 1) * NTOK + i0]     = o[nt][1] * inv0;
        aob[(long)dd * NTOK + i0 + 8]       = o[nt][2] * inv1;
        aob[(long)(dd + 1) * NTOK + i0 + 8] = o[nt][3] * inv1;
    }
}

// ---------------------------------------------------------------------------
extern "C" void kernel_launch(void* const* d_in, const int* in_sizes, int n_in,
                              void* d_out, int out_size)
{
    (void)in_sizes; (void)n_in; (void)out_size;
    const float* fmap  = (const float*)d_in[0];   // [2,256,64,64]
    const float* w_qkv = (const float*)d_in[1];   // [1536,256]
    const float* w_out = (const float*)d_in[2];   // [256,512]
    float* out = (float*)d_out;                   // [2,256,64,64]

    void* qkvPtr = nullptr;
    void* aoPtr  = nullptr;
    cudaGetSymbolAddress(&qkvPtr, g_qkv);
    cudaGetSymbolAddress(&aoPtr,  g_ao);

    const int gemmSmem = (32 * 132 + 128 * 68) * (int)sizeof(float);  // 51712
    cudaFuncSetAttribute(gemm_tc_kernel,
                         cudaFuncAttributeMaxDynamicSharedMemorySize, gemmSmem);

    // K1: QKV projection  [1536,256] @ [2,256,4096] -> g_qkv (3xtf32)
    {
        dim3 grid(NTOK / 64, CQKV / 128, NB);
        gemm_tc_kernel<<<grid, 256, gemmSmem>>>(w_qkv, fmap, (float*)qkvPtr,
                                                CIN, (long)CIN * NTOK, (long)CQKV * NTOK);
    }
    // K2: norms
    norms_kernel<<<(NB * NH * 2 * NTOK) / 256, 256>>>();

    // K3: fp16 m16n8k16 attention
    {
        dim3 grid(NTOK / 128, NH, NB);
        attn_mma_kernel<<<grid, 256>>>();
    }
    // K4: output projection [256,512] @ [2,512,4096] -> out (3xtf32)
    {
        dim3 grid(NTOK / 64, CIN / 128, NB);
        gemm_tc_kernel<<<grid, 256, gemmSmem>>>(w_out, (const float*)aoPtr, out,
                                                CINNER, (long)CINNER * NTOK, (long)CIN * NTOK);
    }
}

// round 8
// speedup vs baseline: 1.6861x; 1.2212x over previous
#include <cuda_runtime.h>
#include <cuda_fp16.h>
#include <cstdint>

// Problem constants
#define NB     2
#define CIN    256
#define NTOK   4096
#define NH     8
#define DH     64
#define CINNER 512         // NH*DH
#define CQKV   1536        // 3*CINNER

// Scratch (allocation-free rule: __device__ globals)
__device__ float g_qkv[NB * CQKV * NTOK];            // [B][1536][N]
__device__ float g_norms[2 * NB * NH * NTOK];        // q2 then k2
__device__ float g_ao[NB * CINNER * NTOK];           // attention output [B][512][N]

// ---------------------------------------------------------------------------
// mma.sync helpers
// ---------------------------------------------------------------------------
__device__ __forceinline__ void mma16(float c[4], const uint32_t a[4],
                                      uint32_t b0, uint32_t b1) {
    asm volatile(
        "mma.sync.aligned.m16n8k16.row.col.f32.f16.f16.f32 "
        "{%0,%1,%2,%3}, {%4,%5,%6,%7}, {%8,%9}, {%0,%1,%2,%3};"
        : "+f"(c[0]), "+f"(c[1]), "+f"(c[2]), "+f"(c[3])
        : "r"(a[0]), "r"(a[1]), "r"(a[2]), "r"(a[3]), "r"(b0), "r"(b1));
}

__device__ __forceinline__ uint32_t packh2(float lo, float hi) {
    __half2 h = __floats2half2_rn(lo, hi);   // .x = lo (low 16 bits)
    return *(uint32_t*)&h;
}

// hi/lo split of two floats (same k-pair) into two half2 words
__device__ __forceinline__ uint2 split2(float e0, float e1) {
    __half h0 = __float2half_rn(e0);
    __half h1 = __float2half_rn(e1);
    float l0 = e0 - __half2float(h0);
    float l1 = e1 - __half2float(h1);
    __half2 hh = __halves2half2(h0, h1);
    __half2 ll = __floats2half2_rn(l0, l1);
    return make_uint2(*(uint32_t*)&hh, *(uint32_t*)&ll);
}

// ---------------------------------------------------------------------------
// 3xfp16 (hi/lo split) tensor-core GEMM, reg-prefetch pipelined.
// Y[b][o][n] = sum_c W[o][c] * X[b][c][n], computed as Y^T: A=X^T, B=W.
// CTA: 256 thr = 8 warps; tile 64(n) x 128(o); warp = 32(n) x 32(o); kTile=32.
// Smem (uint2): XS[cp(16)][72] word(cp,n)={hi2,lo2} of {X[2cp][n],X[2cp+1][n]}
//               WS[cp(16)][136] word(cp,o)={hi2,lo2} of {W[o][2cp],W[o][2cp+1]}
// ---------------------------------------------------------------------------
__global__ void __launch_bounds__(256, 2) gemm_tc_kernel(
    const float* __restrict__ W,  // [M][K]
    const float* __restrict__ X,  // [B][K][NTOK]
    float* __restrict__ Y,        // [B][M][NTOK]
    int K, long xStride, long yStride)
{
    extern __shared__ uint2 sm2[];
    uint2* XS = sm2;              // 16 x 72
    uint2* WS = sm2 + 16 * 72;    // 16 x 136

    const int tid = threadIdx.x;
    const int lane = tid & 31, w = tid >> 5;
    const int quad = lane & 3, g = lane >> 2;
    const int wn = w >> 2, wo = w & 3;
    const int nblk = blockIdx.x * 64;
    const int oblk = blockIdx.y * 128;
    const float* Xb = X + (long)blockIdx.z * xStride;
    float*       Yb = Y + (long)blockIdx.z * yStride;

    // staging coordinates
    const int xrp = tid >> 4;              // c-pair row 0..15
    const int xn4 = (tid & 15) << 2;       // 4 n's
    const int wor = tid >> 1;              // o row 0..127
    const int wch = tid & 1;               // c half (16 c's)
    const float* xsrc = Xb + (long)(2 * xrp) * NTOK + nblk + xn4;
    const float* wsrc = W + (long)(oblk + wor) * K + wch * 16;

    float acc[2][4][4];
    #pragma unroll
    for (int mt = 0; mt < 2; mt++)
        #pragma unroll
        for (int ot = 0; ot < 4; ot++)
            #pragma unroll
            for (int r = 0; r < 4; r++) acc[mt][ot][r] = 0.f;

    // prologue prefetch (kc = 0)
    float4 xr0 = *(const float4*)(xsrc);
    float4 xr1 = *(const float4*)(xsrc + NTOK);
    float4 wr0 = *(const float4*)(wsrc);
    float4 wr1 = *(const float4*)(wsrc + 4);
    float4 wr2 = *(const float4*)(wsrc + 8);
    float4 wr3 = *(const float4*)(wsrc + 12);

    for (int kc = 0; kc < K; kc += 32) {
        __syncthreads();
        // ---- store staged regs, hi/lo fp16 split ----
        {
            float ea[4] = {xr0.x, xr0.y, xr0.z, xr0.w};
            float eb[4] = {xr1.x, xr1.y, xr1.z, xr1.w};
            #pragma unroll
            for (int e = 0; e < 4; e++)
                XS[xrp * 72 + xn4 + e] = split2(ea[e], eb[e]);
        }
        {
            float vv[16] = {wr0.x, wr0.y, wr0.z, wr0.w, wr1.x, wr1.y, wr1.z, wr1.w,
                            wr2.x, wr2.y, wr2.z, wr2.w, wr3.x, wr3.y, wr3.z, wr3.w};
            #pragma unroll
            for (int p = 0; p < 8; p++)
                WS[(8 * wch + p) * 136 + wor] = split2(vv[2 * p], vv[2 * p + 1]);
        }
        __syncthreads();

        // ---- prefetch next k-tile (hidden under compute) ----
        if (kc + 32 < K) {
            const float* xs = xsrc + (long)(kc + 32) * NTOK;
            const float* ws = wsrc + kc + 32;
            xr0 = *(const float4*)(xs);
            xr1 = *(const float4*)(xs + NTOK);
            wr0 = *(const float4*)(ws);
            wr1 = *(const float4*)(ws + 4);
            wr2 = *(const float4*)(ws + 8);
            wr3 = *(const float4*)(ws + 12);
        }

        // ---- compute: 2 k16 steps ----
        #pragma unroll
        for (int s = 0; s < 2; s++) {
            const int cpa = 8 * s + quad;
            uint32_t ah[2][4], al[2][4];
            #pragma unroll
            for (int mt = 0; mt < 2; mt++) {
                int n = 32 * wn + 16 * mt + g;
                uint2 w0 = XS[cpa * 72 + n];
                uint2 w1 = XS[cpa * 72 + n + 8];
                uint2 w2 = XS[(cpa + 4) * 72 + n];
                uint2 w3 = XS[(cpa + 4) * 72 + n + 8];
                ah[mt][0] = w0.x; al[mt][0] = w0.y;
                ah[mt][1] = w1.x; al[mt][1] = w1.y;
                ah[mt][2] = w2.x; al[mt][2] = w2.y;
                ah[mt][3] = w3.x; al[mt][3] = w3.y;
            }
            #pragma unroll
            for (int ot = 0; ot < 4; ot++) {
                int o = 32 * wo + 8 * ot + g;
                uint2 b0 = WS[cpa * 136 + o];
                uint2 b1 = WS[(cpa + 4) * 136 + o];
                #pragma unroll
                for (int mt = 0; mt < 2; mt++) {
                    mma16(acc[mt][ot], al[mt], b0.x, b1.x);   // al*bh
                    mma16(acc[mt][ot], ah[mt], b0.y, b1.y);   // ah*bl
                    mma16(acc[mt][ot], ah[mt], b0.x, b1.x);   // ah*bh
                }
            }
        }
    }

    #pragma unroll
    for (int mt = 0; mt < 2; mt++)
        #pragma unroll
        for (int ot = 0; ot < 4; ot++) {
            int n = nblk + 32 * wn + 16 * mt + g;
            int o = oblk + 32 * wo + 8 * ot + 2 * quad;
            Yb[(long)o * NTOK + n]           = acc[mt][ot][0];
            Yb[(long)(o + 1) * NTOK + n]     = acc[mt][ot][1];
            Yb[(long)o * NTOK + n + 8]       = acc[mt][ot][2];
            Yb[(long)(o + 1) * NTOK + n + 8] = acc[mt][ot][3];
        }
}

// ---------------------------------------------------------------------------
// Norms: q2[b][h][n], k2[b][h][n]
// ---------------------------------------------------------------------------
__global__ void __launch_bounds__(256) norms_kernel()
{
    int idx = blockIdx.x * 256 + threadIdx.x;
    int n = idx & (NTOK - 1);
    int t = idx >> 12;
    int h = t & 7;
    int pb = t >> 3;
    int part = pb & 1;
    int b = pb >> 1;
    const float* p = g_qkv + ((long)(b * CQKV + part * CINNER + h * DH)) * NTOK + n;
    float s = 0.f;
    #pragma unroll
    for (int d = 0; d < DH; d++) { float v = p[(long)d * NTOK]; s = fmaf(v, v, s); }
    g_norms[(long)part * (NB * NH * NTOK) + (long)(b * NH + h) * NTOK + n] = s;
}

// ---------------------------------------------------------------------------
// Flash distance attention via mma.sync fp16 m16n8k16 (f32 accumulate).
// (unchanged from R7 — best-known attention)
// ---------------------------------------------------------------------------
__global__ void __launch_bounds__(256, 2) attn_mma_kernel()
{
    __shared__ uint2 KW[8 * 133];
    __shared__ uint2 VW[8 * 133];
    __shared__ float k2s[64];

    const int tid  = threadIdx.x;
    const int wid  = tid >> 5;
    const int lane = tid & 31;
    const int quad = lane & 3;
    const int g    = lane >> 2;
    const int n0   = blockIdx.x * 128;
    const int h = blockIdx.y, b = blockIdx.z;
    const int bh = b * NH + h;

    const float* qb  = g_qkv + (long)(b * CQKV + h * DH) * NTOK;
    const float* kb  = g_qkv + (long)(b * CQKV + CINNER + h * DH) * NTOK;
    const float* vb  = g_qkv + (long)(b * CQKV + 2 * CINNER + h * DH) * NTOK;
    const float* k2g = g_norms + (long)NB * NH * NTOK + (long)bh * NTOK;

    const int i0 = n0 + wid * 16 + g;

    uint32_t aq[4][4];
    #pragma unroll
    for (int ks = 0; ks < 4; ks++) {
        int d0 = 16 * ks + 2 * quad;
        aq[ks][0] = packh2(qb[(long)d0 * NTOK + i0],       qb[(long)(d0 + 1) * NTOK + i0]);
        aq[ks][1] = packh2(qb[(long)d0 * NTOK + i0 + 8],   qb[(long)(d0 + 1) * NTOK + i0 + 8]);
        aq[ks][2] = packh2(qb[(long)(d0 + 8) * NTOK + i0], qb[(long)(d0 + 9) * NTOK + i0]);
        aq[ks][3] = packh2(qb[(long)(d0 + 8) * NTOK + i0 + 8],
                           qb[(long)(d0 + 9) * NTOK + i0 + 8]);
    }
    const float q2a = g_norms[(long)bh * NTOK + i0];
    const float q2b = g_norms[(long)bh * NTOK + i0 + 8];

    constexpr float LOG2E  = 1.4426950408889634f;
    constexpr float NSHIFT = -12.0f * LOG2E;

    float o[8][4];
    #pragma unroll
    for (int nt = 0; nt < 8; nt++)
        #pragma unroll
        for (int r = 0; r < 4; r++) o[nt][r] = 0.f;
    float lsum0 = 0.f, lsum1 = 0.f;

    uint32_t* KWw = (uint32_t*)KW;
    uint32_t* VWw = (uint32_t*)VW;

    for (int kt = 0; kt < NTOK / 64; kt++) {
        const int nk = kt * 64;
        __syncthreads();

        #pragma unroll
        for (int it = 0; it < 2; it++) {
            int task = tid + it * 256;
            int r = task >> 4, j4 = (task & 15) << 2;
            const float* p0 = kb + (long)(2 * r) * NTOK + nk + j4;
            float4 ka = *(const float4*)p0;
            float4 kc = *(const float4*)(p0 + NTOK);
            float va[4] = {ka.x, ka.y, ka.z, ka.w};
            float vc[4] = {kc.x, kc.y, kc.z, kc.w};
            int ks = r >> 3, q_ = r & 3, wsel = (r >> 2) & 1;
            int base = ks * 33 + q_ * 8;
            #pragma unroll
            for (int s = 0; s < 4; s++) {
                int j = j4 + s;
                KWw[((j >> 3) * 133 + base + (j & 7)) * 2 + wsel] = packh2(va[s], vc[s]);
            }
        }
        #pragma unroll
        for (int it = 0; it < 4; it++) {
            int task = tid + it * 256;
            int dd = task >> 4, j4 = (task & 15) << 2;
            float4 v = *(const float4*)(vb + (long)dd * NTOK + nk + j4);
            int ddnt = dd >> 3, g_ = dd & 7;
            int js = j4 >> 4;
            int p0 = (j4 >> 1) & 7;
            int base = ddnt * 133 + js * 33 + g_ * 4;
            uint32_t w0 = packh2(v.x, v.y);
            uint32_t w1 = packh2(v.z, v.w);
            VWw[(base + (p0 & 3)) * 2 + (p0 >> 2)]             = w0;
            VWw[(base + ((p0 + 1) & 3)) * 2 + ((p0 + 1) >> 2)] = w1;
        }
        if (tid < 64) k2s[tid] = k2g[nk + tid];
        __syncthreads();

        #pragma unroll
        for (int ntp = 0; ntp < 4; ntp++) {
            float c[2][4];
            #pragma unroll
            for (int sub = 0; sub < 2; sub++) {
                int nt = 2 * ntp + sub;
                c[sub][0] = c[sub][1] = c[sub][2] = c[sub][3] = 0.f;
                const uint2* kfp = KW + nt * 133 + quad * 8 + g;
                #pragma unroll
                for (int ks = 0; ks < 4; ks++) {
                    uint2 bb = kfp[ks * 33];
                    mma16(c[sub], aq[ks], bb.x, bb.y);
                }
            }

            float p[2][4];
            #pragma unroll
            for (int sub = 0; sub < 2; sub++) {
                int nt = 2 * ntp + sub;
                float k2c0 = k2s[8 * nt + 2 * quad];
                float k2c1 = k2s[8 * nt + 2 * quad + 1];
                float d2, s;
                d2 = fmaxf(q2a + k2c0 - 2.f * c[sub][0], 0.f);
                asm("sqrt.approx.f32 %0, %1;" : "=f"(s) : "f"(d2));
                asm("ex2.approx.f32 %0, %1;" : "=f"(p[sub][0]) : "f"(fmaf(s, LOG2E, NSHIFT)));
                d2 = fmaxf(q2a + k2c1 - 2.f * c[sub][1], 0.f);
                asm("sqrt.approx.f32 %0, %1;" : "=f"(s) : "f"(d2));
                asm("ex2.approx.f32 %0, %1;" : "=f"(p[sub][1]) : "f"(fmaf(s, LOG2E, NSHIFT)));
                d2 = fmaxf(q2b + k2c0 - 2.f * c[sub][2], 0.f);
                asm("sqrt.approx.f32 %0, %1;" : "=f"(s) : "f"(d2));
                asm("ex2.approx.f32 %0, %1;" : "=f"(p[sub][2]) : "f"(fmaf(s, LOG2E, NSHIFT)));
                d2 = fmaxf(q2b + k2c1 - 2.f * c[sub][3], 0.f);
                asm("sqrt.approx.f32 %0, %1;" : "=f"(s) : "f"(d2));
                asm("ex2.approx.f32 %0, %1;" : "=f"(p[sub][3]) : "f"(fmaf(s, LOG2E, NSHIFT)));
                lsum0 += p[sub][0] + p[sub][1];
                lsum1 += p[sub][2] + p[sub][3];
            }

            uint32_t ap[4];
            ap[0] = packh2(p[0][0], p[0][1]);
            ap[1] = packh2(p[0][2], p[0][3]);
            ap[2] = packh2(p[1][0], p[1][1]);
            ap[3] = packh2(p[1][2], p[1][3]);

            const uint2* vfp = VW + ntp * 33 + lane;
            #pragma unroll
            for (int ddnt = 0; ddnt < 8; ddnt++) {
                uint2 vv = vfp[ddnt * 133];
                mma16(o[ddnt], ap, vv.x, vv.y);
            }
        }
    }

    lsum0 += __shfl_xor_sync(0xffffffffu, lsum0, 1);
    lsum0 += __shfl_xor_sync(0xffffffffu, lsum0, 2);
    lsum1 += __shfl_xor_sync(0xffffffffu, lsum1, 1);
    lsum1 += __shfl_xor_sync(0xffffffffu, lsum1, 2);
    const float inv0 = 1.f / lsum0;
    const float inv1 = 1.f / lsum1;

    float* aob = g_ao + (long)(b * CINNER + h * DH) * NTOK;
    #pragma unroll
    for (int nt = 0; nt < 8; nt++) {
        int dd = 8 * nt + 2 * quad;
        aob[(long)dd * NTOK + i0]           = o[nt][0] * inv0;
        aob[(long)(dd + 1) * NTOK + i0]     = o[nt][1] * inv0;
        aob[(long)dd * NTOK + i0 + 8]       = o[nt][2] * inv1;
        aob[(long)(dd + 1) * NTOK + i0 + 8] = o[nt][3] * inv1;
    }
}

// ---------------------------------------------------------------------------
extern "C" void kernel_launch(void* const* d_in, const int* in_sizes, int n_in,
                              void* d_out, int out_size)
{
    (void)in_sizes; (void)n_in; (void)out_size;
    const float* fmap  = (const float*)d_in[0];   // [2,256,64,64]
    const float* w_qkv = (const float*)d_in[1];   // [1536,256]
    const float* w_out = (const float*)d_in[2];   // [256,512]
    float* out = (float*)d_out;                   // [2,256,64,64]

    void* qkvPtr = nullptr;
    void* aoPtr  = nullptr;
    cudaGetSymbolAddress(&qkvPtr, g_qkv);
    cudaGetSymbolAddress(&aoPtr,  g_ao);

    const int gemmSmem = (16 * 72 + 16 * 136) * 8;   // 26624 B
    cudaFuncSetAttribute(gemm_tc_kernel,
                         cudaFuncAttributeMaxDynamicSharedMemorySize, gemmSmem);

    // K1: QKV projection  [1536,256] @ [2,256,4096] -> g_qkv (3xfp16 hi/lo)
    {
        dim3 grid(NTOK / 64, CQKV / 128, NB);
        gemm_tc_kernel<<<grid, 256, gemmSmem>>>(w_qkv, fmap, (float*)qkvPtr,
                                                CIN, (long)CIN * NTOK, (long)CQKV * NTOK);
    }
    // K2: norms
    norms_kernel<<<(NB * NH * 2 * NTOK) / 256, 256>>>();

    // K3: fp16 m16n8k16 attention
    {
        dim3 grid(NTOK / 128, NH, NB);
        attn_mma_kernel<<<grid, 256>>>();
    }
    // K4: output projection [256,512] @ [2,512,4096] -> out (3xfp16 hi/lo)
    {
        dim3 grid(NTOK / 64, CIN / 128, NB);
        gemm_tc_kernel<<<grid, 256, gemmSmem>>>(w_out, (const float*)aoPtr, out,
                                                CINNER, (long)CINNER * NTOK, (long)CIN * NTOK);
    }
}

// round 9
// speedup vs baseline: 2.1147x; 1.2542x over previous
#include <cuda_runtime.h>
#include <cuda_fp16.h>
#include <cstdint>

// Problem constants
#define NB     2
#define CIN    256
#define NTOK   4096
#define NH     8
#define DH     64
#define CINNER 512         // NH*DH
#define CQKV   1536        // 3*CINNER
#define NKT    (NTOK / 64) // 64 key tiles

// Scratch (allocation-free rule: __device__ globals)
__device__ float g_qkv[NB * CQKV * NTOK];            // [B][1536][N]
__device__ float g_norms[2 * NB * NH * NTOK];        // q2 then k2
__device__ float g_ao[NB * CINNER * NTOK];           // attention output [B][512][N]
// fp16 fragment-ordered K/V: [bh][kt][1024] uint2 (8KB per tile)
__device__ uint2 g_kf[NB * NH * NKT * 1024];
__device__ uint2 g_vf[NB * NH * NKT * 1024];

// ---------------------------------------------------------------------------
// helpers
// ---------------------------------------------------------------------------
__device__ __forceinline__ void mma16(float c[4], const uint32_t a[4],
                                      uint32_t b0, uint32_t b1) {
    asm volatile(
        "mma.sync.aligned.m16n8k16.row.col.f32.f16.f16.f32 "
        "{%0,%1,%2,%3}, {%4,%5,%6,%7}, {%8,%9}, {%0,%1,%2,%3};"
        : "+f"(c[0]), "+f"(c[1]), "+f"(c[2]), "+f"(c[3])
        : "r"(a[0]), "r"(a[1]), "r"(a[2]), "r"(a[3]), "r"(b0), "r"(b1));
}

__device__ __forceinline__ uint32_t packh2(float lo, float hi) {
    __half2 h = __floats2half2_rn(lo, hi);   // .x = lo (low 16 bits)
    return *(uint32_t*)&h;
}

__device__ __forceinline__ uint2 split2(float e0, float e1) {
    __half h0 = __float2half_rn(e0);
    __half h1 = __float2half_rn(e1);
    float l0 = e0 - __half2float(h0);
    float l1 = e1 - __half2float(h1);
    __half2 hh = __halves2half2(h0, h1);
    __half2 ll = __floats2half2_rn(l0, l1);
    return make_uint2(*(uint32_t*)&hh, *(uint32_t*)&ll);
}

__device__ __forceinline__ uint32_t smem_u32(const void* p) {
    uint32_t a;
    asm("{ .reg .u64 t; cvta.to.shared.u64 t, %1; cvt.u32.u64 %0, t; }"
        : "=r"(a) : "l"(p));
    return a;
}

__device__ __forceinline__ void cp16(uint32_t dst, const void* src) {
    asm volatile("cp.async.cg.shared.global [%0], [%1], 16;"
                 :: "r"(dst), "l"(src) : "memory");
}
#define CP_COMMIT() asm volatile("cp.async.commit_group;" ::: "memory")
#define CP_WAIT(n)  asm volatile("cp.async.wait_group %0;" :: "n"(n) : "memory")

// ---------------------------------------------------------------------------
// 3xfp16 (hi/lo split) tensor-core GEMM (unchanged from R8)
// ---------------------------------------------------------------------------
__global__ void __launch_bounds__(256, 2) gemm_tc_kernel(
    const float* __restrict__ W, const float* __restrict__ X, float* __restrict__ Y,
    int K, long xStride, long yStride)
{
    extern __shared__ uint2 sm2[];
    uint2* XS = sm2;              // 16 x 72
    uint2* WS = sm2 + 16 * 72;    // 16 x 136

    const int tid = threadIdx.x;
    const int lane = tid & 31, w = tid >> 5;
    const int quad = lane & 3, g = lane >> 2;
    const int wn = w >> 2, wo = w & 3;
    const int nblk = blockIdx.x * 64;
    const int oblk = blockIdx.y * 128;
    const float* Xb = X + (long)blockIdx.z * xStride;
    float*       Yb = Y + (long)blockIdx.z * yStride;

    const int xrp = tid >> 4;
    const int xn4 = (tid & 15) << 2;
    const int wor = tid >> 1;
    const int wch = tid & 1;
    const float* xsrc = Xb + (long)(2 * xrp) * NTOK + nblk + xn4;
    const float* wsrc = W + (long)(oblk + wor) * K + wch * 16;

    float acc[2][4][4];
    #pragma unroll
    for (int mt = 0; mt < 2; mt++)
        #pragma unroll
        for (int ot = 0; ot < 4; ot++)
            #pragma unroll
            for (int r = 0; r < 4; r++) acc[mt][ot][r] = 0.f;

    float4 xr0 = *(const float4*)(xsrc);
    float4 xr1 = *(const float4*)(xsrc + NTOK);
    float4 wr0 = *(const float4*)(wsrc);
    float4 wr1 = *(const float4*)(wsrc + 4);
    float4 wr2 = *(const float4*)(wsrc + 8);
    float4 wr3 = *(const float4*)(wsrc + 12);

    for (int kc = 0; kc < K; kc += 32) {
        __syncthreads();
        {
            float ea[4] = {xr0.x, xr0.y, xr0.z, xr0.w};
            float eb[4] = {xr1.x, xr1.y, xr1.z, xr1.w};
            #pragma unroll
            for (int e = 0; e < 4; e++)
                XS[xrp * 72 + xn4 + e] = split2(ea[e], eb[e]);
        }
        {
            float vv[16] = {wr0.x, wr0.y, wr0.z, wr0.w, wr1.x, wr1.y, wr1.z, wr1.w,
                            wr2.x, wr2.y, wr2.z, wr2.w, wr3.x, wr3.y, wr3.z, wr3.w};
            #pragma unroll
            for (int p = 0; p < 8; p++)
                WS[(8 * wch + p) * 136 + wor] = split2(vv[2 * p], vv[2 * p + 1]);
        }
        __syncthreads();

        if (kc + 32 < K) {
            const float* xs = xsrc + (long)(kc + 32) * NTOK;
            const float* ws = wsrc + kc + 32;
            xr0 = *(const float4*)(xs);
            xr1 = *(const float4*)(xs + NTOK);
            wr0 = *(const float4*)(ws);
            wr1 = *(const float4*)(ws + 4);
            wr2 = *(const float4*)(ws + 8);
            wr3 = *(const float4*)(ws + 12);
        }

        #pragma unroll
        for (int s = 0; s < 2; s++) {
            const int cpa = 8 * s + quad;
            uint32_t ah[2][4], al[2][4];
            #pragma unroll
            for (int mt = 0; mt < 2; mt++) {
                int n = 32 * wn + 16 * mt + g;
                uint2 w0 = XS[cpa * 72 + n];
                uint2 w1 = XS[cpa * 72 + n + 8];
                uint2 w2 = XS[(cpa + 4) * 72 + n];
                uint2 w3 = XS[(cpa + 4) * 72 + n + 8];
                ah[mt][0] = w0.x; al[mt][0] = w0.y;
                ah[mt][1] = w1.x; al[mt][1] = w1.y;
                ah[mt][2] = w2.x; al[mt][2] = w2.y;
                ah[mt][3] = w3.x; al[mt][3] = w3.y;
            }
            #pragma unroll
            for (int ot = 0; ot < 4; ot++) {
                int o = 32 * wo + 8 * ot + g;
                uint2 b0 = WS[cpa * 136 + o];
                uint2 b1 = WS[(cpa + 4) * 136 + o];
                #pragma unroll
                for (int mt = 0; mt < 2; mt++) {
                    mma16(acc[mt][ot], al[mt], b0.x, b1.x);
                    mma16(acc[mt][ot], ah[mt], b0.y, b1.y);
                    mma16(acc[mt][ot], ah[mt], b0.x, b1.x);
                }
            }
        }
    }

    #pragma unroll
    for (int mt = 0; mt < 2; mt++)
        #pragma unroll
        for (int ot = 0; ot < 4; ot++) {
            int n = nblk + 32 * wn + 16 * mt + g;
            int o = oblk + 32 * wo + 8 * ot + 2 * quad;
            Yb[(long)o * NTOK + n]           = acc[mt][ot][0];
            Yb[(long)(o + 1) * NTOK + n]     = acc[mt][ot][1];
            Yb[(long)o * NTOK + n + 8]       = acc[mt][ot][2];
            Yb[(long)(o + 1) * NTOK + n + 8] = acc[mt][ot][3];
        }
}

// ---------------------------------------------------------------------------
// Norms: q2[b][h][n], k2[b][h][n]
// ---------------------------------------------------------------------------
__global__ void __launch_bounds__(256) norms_kernel()
{
    int idx = blockIdx.x * 256 + threadIdx.x;
    int n = idx & (NTOK - 1);
    int t = idx >> 12;
    int h = t & 7;
    int pb = t >> 3;
    int part = pb & 1;
    int b = pb >> 1;
    const float* p = g_qkv + ((long)(b * CQKV + part * CINNER + h * DH)) * NTOK + n;
    float s = 0.f;
    #pragma unroll
    for (int d = 0; d < DH; d++) { float v = p[(long)d * NTOK]; s = fmaf(v, v, s); }
    g_norms[(long)part * (NB * NH * NTOK) + (long)(b * NH + h) * NTOK + n] = s;
}

// ---------------------------------------------------------------------------
// Fragment pre-conversion: K,V (fp32, d-major in g_qkv) -> fp16 mma-fragment
// order in g_kf/g_vf. One block per (kt, bh, K|V); 1024 uint2 words per tile.
// Word w: lane=w&31 (quad=lane&3, g=lane>>2) holds B-frag pair content.
//   K (w>>7=nt, (w>>5)&3=ks):  x=h2{K[16ks+2q][8nt+g+nk], K[16ks+2q+1][..]}, y=+8 d
//   V (w>>8=js, (w>>5)&7=ddnt): x=h2{V[8ddnt+g][nk+16js+2q], V[..][+1]},     y=+8 keys
// ---------------------------------------------------------------------------
__global__ void __launch_bounds__(256) frag_kernel()
{
    const int kt = blockIdx.x, bh = blockIdx.y, isV = blockIdx.z;
    const int b = bh >> 3, h = bh & 7;
    const int nk = kt * 64;
    const float* src = g_qkv + (long)(b * CQKV + (isV ? 2 : 1) * CINNER + h * DH) * NTOK;
    uint2* dst = (isV ? g_vf : g_kf) + ((long)bh * NKT + kt) * 1024;

    #pragma unroll
    for (int it = 0; it < 4; it++) {
        int w = threadIdx.x + it * 256;
        int lane = w & 31, quad = lane & 3, g = lane >> 2;
        uint2 r;
        if (!isV) {
            int nt = w >> 7, ks = (w >> 5) & 3;
            int d0 = 16 * ks + 2 * quad;
            int j = nk + 8 * nt + g;
            r.x = packh2(src[(long)d0 * NTOK + j],       src[(long)(d0 + 1) * NTOK + j]);
            r.y = packh2(src[(long)(d0 + 8) * NTOK + j], src[(long)(d0 + 9) * NTOK + j]);
        } else {
            int js = w >> 8, ddnt = (w >> 5) & 7;
            int dd = 8 * ddnt + g;
            int key0 = nk + 16 * js + 2 * quad;
            float2 v0 = *(const float2*)&src[(long)dd * NTOK + key0];
            float2 v1 = *(const float2*)&src[(long)dd * NTOK + key0 + 8];
            r.x = packh2(v0.x, v0.y);
            r.y = packh2(v1.x, v1.y);
        }
        dst[w] = r;
    }
}

// ---------------------------------------------------------------------------
// Flash distance attention: fp16 m16n8k16, pre-fragmented K/V via cp.async
// double buffering. CTA = 256 thr = 8 warps x 16 query rows (128 q / CTA).
// Fixed-shift softmax (scores bounded): no row max, no rescale.
// ---------------------------------------------------------------------------
__global__ void __launch_bounds__(256, 2) attn_mma_kernel()
{
    __shared__ uint4 KFs[2][512];    // 2 x 8KB
    __shared__ uint4 VFs[2][512];    // 2 x 8KB
    __shared__ float k2ss[2][64];

    const int tid  = threadIdx.x;
    const int wid  = tid >> 5;
    const int lane = tid & 31;
    const int quad = lane & 3;
    const int g    = lane >> 2;
    const int n0   = blockIdx.x * 128;
    const int h = blockIdx.y, b = blockIdx.z;
    const int bh = b * NH + h;

    const float* qb  = g_qkv + (long)(b * CQKV + h * DH) * NTOK;
    const float* k2g = g_norms + (long)NB * NH * NTOK + (long)bh * NTOK;
    const uint4* kfg = (const uint4*)(g_kf + (long)bh * NKT * 1024);
    const uint4* vfg = (const uint4*)(g_vf + (long)bh * NKT * 1024);

    const uint32_t kfS = smem_u32(KFs);
    const uint32_t vfS = smem_u32(VFs);
    const uint32_t k2S = smem_u32(k2ss);

    const int i0 = n0 + wid * 16 + g;

    // Q A-fragments (fp16)
    uint32_t aq[4][4];
    #pragma unroll
    for (int ks = 0; ks < 4; ks++) {
        int d0 = 16 * ks + 2 * quad;
        aq[ks][0] = packh2(qb[(long)d0 * NTOK + i0],       qb[(long)(d0 + 1) * NTOK + i0]);
        aq[ks][1] = packh2(qb[(long)d0 * NTOK + i0 + 8],   qb[(long)(d0 + 1) * NTOK + i0 + 8]);
        aq[ks][2] = packh2(qb[(long)(d0 + 8) * NTOK + i0], qb[(long)(d0 + 9) * NTOK + i0]);
        aq[ks][3] = packh2(qb[(long)(d0 + 8) * NTOK + i0 + 8],
                           qb[(long)(d0 + 9) * NTOK + i0 + 8]);
    }
    const float q2a = g_norms[(long)bh * NTOK + i0];
    const float q2b = g_norms[(long)bh * NTOK + i0 + 8];

    constexpr float LOG2E  = 1.4426950408889634f;
    constexpr float NSHIFT = -12.0f * LOG2E;

    float o[8][4];
    #pragma unroll
    for (int nt = 0; nt < 8; nt++)
        #pragma unroll
        for (int r = 0; r < 4; r++) o[nt][r] = 0.f;
    float lsum0 = 0.f, lsum1 = 0.f;

    // ---- stage helper: 4 cp16 for K/V tiles + 1 for k2 (threads 0..15) ----
    auto stage = [&](int kt, int buf) {
        const uint4* ks_ = kfg + (long)kt * 512;
        const uint4* vs_ = vfg + (long)kt * 512;
        uint32_t kd = kfS + (uint32_t)buf * 8192u + (uint32_t)tid * 16u;
        uint32_t vd = vfS + (uint32_t)buf * 8192u + (uint32_t)tid * 16u;
        cp16(kd,         ks_ + tid);
        cp16(kd + 4096u, ks_ + 256 + tid);
        cp16(vd,         vs_ + tid);
        cp16(vd + 4096u, vs_ + 256 + tid);
        if (tid < 16)
            cp16(k2S + (uint32_t)buf * 256u + (uint32_t)tid * 16u,
                 (const float4*)(k2g + kt * 64) + tid);
        CP_COMMIT();
    };

    stage(0, 0);

    for (int kt = 0; kt < NKT; kt++) {
        const int buf = kt & 1;
        CP_WAIT(0);
        __syncthreads();     // tile kt visible; all warps done with buf^1
        if (kt + 1 < NKT) stage(kt + 1, buf ^ 1);

        const uint2* KB = (const uint2*)KFs[buf];
        const uint2* VB = (const uint2*)VFs[buf];
        const float* k2p = k2ss[buf];

        #pragma unroll
        for (int ntp = 0; ntp < 4; ntp++) {
            float c[2][4];
            #pragma unroll
            for (int sub = 0; sub < 2; sub++) {
                int nt = 2 * ntp + sub;
                c[sub][0] = c[sub][1] = c[sub][2] = c[sub][3] = 0.f;
                const uint2* kfp = KB + nt * 128 + lane;
                #pragma unroll
                for (int ks = 0; ks < 4; ks++) {
                    uint2 bb = kfp[ks * 32];
                    mma16(c[sub], aq[ks], bb.x, bb.y);
                }
            }

            float p[2][4];
            #pragma unroll
            for (int sub = 0; sub < 2; sub++) {
                int nt = 2 * ntp + sub;
                float2 k2c = *(const float2*)&k2p[8 * nt + 2 * quad];
                float a0 = q2a + k2c.x, a1 = q2a + k2c.y;
                float b0_ = q2b + k2c.x, b1_ = q2b + k2c.y;
                float d2, s;
                d2 = fmaxf(fmaf(-2.f, c[sub][0], a0), 0.f);
                asm("sqrt.approx.f32 %0, %1;" : "=f"(s) : "f"(d2));
                asm("ex2.approx.f32 %0, %1;" : "=f"(p[sub][0]) : "f"(fmaf(s, LOG2E, NSHIFT)));
                d2 = fmaxf(fmaf(-2.f, c[sub][1], a1), 0.f);
                asm("sqrt.approx.f32 %0, %1;" : "=f"(s) : "f"(d2));
                asm("ex2.approx.f32 %0, %1;" : "=f"(p[sub][1]) : "f"(fmaf(s, LOG2E, NSHIFT)));
                d2 = fmaxf(fmaf(-2.f, c[sub][2], b0_), 0.f);
                asm("sqrt.approx.f32 %0, %1;" : "=f"(s) : "f"(d2));
                asm("ex2.approx.f32 %0, %1;" : "=f"(p[sub][2]) : "f"(fmaf(s, LOG2E, NSHIFT)));
                d2 = fmaxf(fmaf(-2.f, c[sub][3], b1_), 0.f);
                asm("sqrt.approx.f32 %0, %1;" : "=f"(s) : "f"(d2));
                asm("ex2.approx.f32 %0, %1;" : "=f"(p[sub][3]) : "f"(fmaf(s, LOG2E, NSHIFT)));
                lsum0 += p[sub][0] + p[sub][1];
                lsum1 += p[sub][2] + p[sub][3];
            }

            uint32_t ap[4];
            ap[0] = packh2(p[0][0], p[0][1]);
            ap[1] = packh2(p[0][2], p[0][3]);
            ap[2] = packh2(p[1][0], p[1][1]);
            ap[3] = packh2(p[1][2], p[1][3]);

            const uint2* vfp = VB + ntp * 256 + lane;
            #pragma unroll
            for (int ddnt = 0; ddnt < 8; ddnt++) {
                uint2 vv = vfp[ddnt * 32];
                mma16(o[ddnt], ap, vv.x, vv.y);
            }
        }
    }

    lsum0 += __shfl_xor_sync(0xffffffffu, lsum0, 1);
    lsum0 += __shfl_xor_sync(0xffffffffu, lsum0, 2);
    lsum1 += __shfl_xor_sync(0xffffffffu, lsum1, 1);
    lsum1 += __shfl_xor_sync(0xffffffffu, lsum1, 2);
    const float inv0 = 1.f / lsum0;
    const float inv1 = 1.f / lsum1;

    float* aob = g_ao + (long)(b * CINNER + h * DH) * NTOK;
    #pragma unroll
    for (int nt = 0; nt < 8; nt++) {
        int dd = 8 * nt + 2 * quad;
        aob[(long)dd * NTOK + i0]           = o[nt][0] * inv0;
        aob[(long)(dd + 1) * NTOK + i0]     = o[nt][1] * inv0;
        aob[(long)dd * NTOK + i0 + 8]       = o[nt][2] * inv1;
        aob[(long)(dd + 1) * NTOK + i0 + 8] = o[nt][3] * inv1;
    }
}

// ---------------------------------------------------------------------------
extern "C" void kernel_launch(void* const* d_in, const int* in_sizes, int n_in,
                              void* d_out, int out_size)
{
    (void)in_sizes; (void)n_in; (void)out_size;
    const float* fmap  = (const float*)d_in[0];   // [2,256,64,64]
    const float* w_qkv = (const float*)d_in[1];   // [1536,256]
    const float* w_out = (const float*)d_in[2];   // [256,512]
    float* out = (float*)d_out;                   // [2,256,64,64]

    void* qkvPtr = nullptr;
    void* aoPtr  = nullptr;
    cudaGetSymbolAddress(&qkvPtr, g_qkv);
    cudaGetSymbolAddress(&aoPtr,  g_ao);

    const int gemmSmem = (16 * 72 + 16 * 136) * 8;   // 26624 B
    cudaFuncSetAttribute(gemm_tc_kernel,
                         cudaFuncAttributeMaxDynamicSharedMemorySize, gemmSmem);

    // K1: QKV projection (3xfp16 hi/lo)
    {
        dim3 grid(NTOK / 64, CQKV / 128, NB);
        gemm_tc_kernel<<<grid, 256, gemmSmem>>>(w_qkv, fmap, (float*)qkvPtr,
                                                CIN, (long)CIN * NTOK, (long)CQKV * NTOK);
    }
    // K2: norms
    norms_kernel<<<(NB * NH * 2 * NTOK) / 256, 256>>>();

    // K2.5: K/V fragment pre-conversion
    {
        dim3 grid(NKT, NB * NH, 2);
        frag_kernel<<<grid, 256>>>();
    }
    // K3: fp16 attention with cp.async fragments
    {
        dim3 grid(NTOK / 128, NH, NB);
        attn_mma_kernel<<<grid, 256>>>();
    }
    // K4: output projection (3xfp16 hi/lo)
    {
        dim3 grid(NTOK / 64, CIN / 128, NB);
        gemm_tc_kernel<<<grid, 256, gemmSmem>>>(w_out, (const float*)aoPtr, out,
                                                CINNER, (long)CINNER * NTOK, (long)CIN * NTOK);
    }
}